// round 9
// baseline (speedup 1.0000x reference)
#include <cuda_runtime.h>
#include <cuda_bf16.h>
#include <mma.h>
#include <math.h>

using namespace nvcuda;

#define D_DIM 128
#define V_DIM 100000
#define N_DIM 20000
#define E_DIM 640000
#define NODES_PER_BLK 32
#define NTILES (N_DIM / NODES_PER_BLK)     // 625, exact
#define GNODES 8                            // nodes per gather block (warp/node)
#define GBLKS  (N_DIM / GNODES)             // 2500, exact
#define GIDX_CAP 768                        // staged idx per gather block (mean 256)

// padded strides (conflict-free LDSM: 528B row shift = 4 banks)
#define SA 264                  // bf16 elems per A row (528 B)
#define SC 132                  // float elems per C row (528 B)
#define A_BYTES   (NODES_PER_BLK * SA * 2)       // 16896 (== 32*SC*4, C overlay)

// prep kernel block ranges
#define EPACK_T      400000     // float4 stride; 8 per thread -> 3.2M total
#define EPACK_BLOCKS 1563       // ceil(400000/256)
#define WM_BLOCKS    32
#define RP_BLOCKS    2500
#define PREP_BLOCKS  (EPACK_BLOCKS + WM_BLOCKS + RP_BLOCKS)

// ---------------- scratch (device globals; no runtime allocation) ----------
__device__ int   g_rowptr[N_DIM + 1];
__device__ __nv_bfloat16 g_embh[(size_t)V_DIM * D_DIM];      // 25.6 MB bf16 table
__device__ __nv_bfloat16 g_wm[D_DIM * 2 * D_DIM];            // [128][256] bf16
__device__ __nv_bfloat16 g_abuf[(size_t)N_DIM * 2 * D_DIM];  // 10.24 MB [self|agg]
__device__ float g_partials[NTILES * D_DIM];

// ---------------- K1: prep (pack emb->bf16, pack [W|M], rowptr) ------------
__global__ void prep_kernel(const float* __restrict__ emb,
                            const float* __restrict__ W,
                            const float* __restrict__ M,
                            const int* __restrict__ seg) {
    const int b   = blockIdx.x;
    const int tid = threadIdx.x;

    if (b < EPACK_BLOCKS) {
        const int t = b * 256 + tid;              // 0 .. 400127
        if (t < EPACK_T) {
            const float4* src = (const float4*)emb;
            float4 v[8];
            #pragma unroll
            for (int k = 0; k < 8; ++k)
                v[k] = __ldg(src + t + k * EPACK_T);
            #pragma unroll
            for (int k = 0; k < 8; ++k) {
                __nv_bfloat162 lo = __float22bfloat162_rn(make_float2(v[k].x, v[k].y));
                __nv_bfloat162 hi = __float22bfloat162_rn(make_float2(v[k].z, v[k].w));
                uint2 u;
                u.x = *(unsigned int*)&lo;
                u.y = *(unsigned int*)&hi;
                ((uint2*)g_embh)[t + k * EPACK_T] = u;
            }
        }
    } else if (b < EPACK_BLOCKS + WM_BLOCKS) {
        int base = (b - EPACK_BLOCKS) * 256 + tid;
        #pragma unroll
        for (int rep = 0; rep < 4; ++rep) {
            int i = base + rep * 8192;            // 0..32767
            int d = i >> 8;
            int k = i & 255;
            float v = (k < D_DIM) ? __ldg(&W[d * D_DIM + k])
                                  : __ldg(&M[d * D_DIM + (k - D_DIM)]);
            g_wm[i] = __float2bfloat16(v);
        }
    } else {
        int e = (b - EPACK_BLOCKS - WM_BLOCKS) * 256 + tid;
        if (e >= E_DIM) return;
        int s = __ldg(&seg[e]);
        if (e == 0) {
            for (int t = 0; t <= s; ++t) g_rowptr[t] = 0;
        } else {
            int p = __ldg(&seg[e - 1]);
            for (int t = p + 1; t <= s; ++t) g_rowptr[t] = e;
        }
        if (e == E_DIM - 1) {
            for (int t = s + 1; t <= N_DIM; ++t) g_rowptr[t] = E_DIM;
        }
    }
}

// ---------------- helpers ---------------------------------------------------
__device__ __forceinline__ void acc_bf4(float acc[4], uint2 v) {
    float2 f0 = __bfloat1622float2(*(__nv_bfloat162*)&v.x);
    float2 f1 = __bfloat1622float2(*(__nv_bfloat162*)&v.y);
    acc[0] += f0.x; acc[1] += f0.y;
    acc[2] += f1.x; acc[3] += f1.y;
}

__device__ __forceinline__ uint2 pack_bf4(const float acc[4]) {
    __nv_bfloat162 b0 = __float22bfloat162_rn(make_float2(acc[0], acc[1]));
    __nv_bfloat162 b1 = __float22bfloat162_rn(make_float2(acc[2], acc[3]));
    uint2 u;
    u.x = *(unsigned int*)&b0;
    u.y = *(unsigned int*)&b1;
    return u;
}

// ---------------- K2: gather + segment-sum -> g_abuf (bf16, gemm-ready) ----
// Warp-per-node, 8 nodes per block, 2500 blocks. Lean registers -> high
// occupancy: ~40 resident warps/SM, each holding 8 independent LDG.64
// gathers in flight -> L2-BW-bound. Indices staged in smem (no global
// idx->gather chain).
__global__ __launch_bounds__(256, 5)
void gather_kernel(const int* __restrict__ node_ids,
                   const int* __restrict__ nbr) {
    __shared__ int idx_s[GIDX_CAP];

    const int tid  = threadIdx.x;
    const int w    = tid >> 5;
    const int lane = tid & 31;
    const int n    = blockIdx.x * GNODES + w;

    // stage the block's contiguous edge-index range
    const int estart = g_rowptr[blockIdx.x * GNODES];
    const int ecnt   = g_rowptr[blockIdx.x * GNODES + GNODES] - estart;
    const bool all_staged = (ecnt <= GIDX_CAP);
    const int scnt = all_staged ? ecnt : GIDX_CAP;
    for (int j = tid; j < scnt; j += 256)
        idx_s[j] = __ldg(&nbr[estart + j]);
    __syncthreads();

    // self row: straight bf16 copy
    {
        int nid = __ldg(&node_ids[n]);
        uint2 sv = __ldg(((const uint2*)(g_embh + (size_t)nid * D_DIM)) + lane);
        ((uint2*)(g_abuf + (size_t)n * 2 * D_DIM))[lane] = sv;
    }

    float acc[4] = {0.f, 0.f, 0.f, 0.f};
    const int js = g_rowptr[n]     - estart;
    const int je = g_rowptr[n + 1] - estart;

    if (all_staged) {
        int j = js;
        for (; j + 8 <= je; j += 8) {
            int ix[8];
            #pragma unroll
            for (int k = 0; k < 8; ++k) ix[k] = idx_s[j + k];
            uint2 v[8];
            #pragma unroll
            for (int k = 0; k < 8; ++k)
                v[k] = __ldg(((const uint2*)(g_embh + (size_t)ix[k] * D_DIM)) + lane);
            #pragma unroll
            for (int k = 0; k < 8; ++k) acc_bf4(acc, v[k]);
        }
        for (; j < je; ++j) {
            uint2 v = __ldg(((const uint2*)(g_embh + (size_t)idx_s[j] * D_DIM)) + lane);
            acc_bf4(acc, v);
        }
    } else {
        for (int j = js; j < je; ++j) {
            int ix = (j < GIDX_CAP) ? idx_s[j] : __ldg(&nbr[estart + j]);
            uint2 v = __ldg(((const uint2*)(g_embh + (size_t)ix * D_DIM)) + lane);
            acc_bf4(acc, v);
        }
    }
    ((uint2*)(g_abuf + (size_t)n * 2 * D_DIM + D_DIM))[lane] = pack_bf4(acc);
}

// ---------------- K3: streaming GEMM relu colsum over g_abuf ---------------
// 625 blocks x 256 threads. A tile [32][256] bf16 loaded coalesced (2 uint4
// per thread), wmma per warp (cols [16w,16w+16)), relu, column-sum.
__global__ __launch_bounds__(256)
void gemm_kernel() {
    extern __shared__ unsigned char dynsmem[];
    __nv_bfloat16* As = (__nv_bfloat16*)dynsmem;   // [32][SA]
    float*         Cs = (float*)dynsmem;           // [32][SC] (overlay)
    __shared__ float red[256];

    const int tid = threadIdx.x;
    const int w   = tid >> 5;
    const int n0  = blockIdx.x * NODES_PER_BLK;

    // load A tile: 32 rows x 512B = 1024 uint4, coalesced
    {
        const uint4* src = (const uint4*)(g_abuf + (size_t)n0 * 2 * D_DIM);
        #pragma unroll
        for (int k = 0; k < 4; ++k) {
            int u = tid + k * 256;        // 0..1023
            int row = u >> 5, col = u & 31;
            *(uint4*)(As + row * SA + col * 8) = __ldg(src + u);
        }
    }
    __syncthreads();

    // MMA: warp w -> cols [16w,16w+16) x rows 0..31
    wmma::fragment<wmma::accumulator, 16, 16, 16, float> c0f, c1f;
    wmma::fill_fragment(c0f, 0.0f);
    wmma::fill_fragment(c1f, 0.0f);

    #pragma unroll
    for (int kk = 0; kk < 16; ++kk) {
        wmma::fragment<wmma::matrix_b, 16, 16, 16, __nv_bfloat16, wmma::col_major> bf;
        wmma::load_matrix_sync(bf, g_wm + (w * 16) * 256 + kk * 16, 256);
        wmma::fragment<wmma::matrix_a, 16, 16, 16, __nv_bfloat16, wmma::row_major> a0, a1;
        wmma::load_matrix_sync(a0, As + kk * 16, SA);           // rows 0-15
        wmma::load_matrix_sync(a1, As + 16 * SA + kk * 16, SA); // rows 16-31
        wmma::mma_sync(c0f, a0, bf, c0f);
        wmma::mma_sync(c1f, a1, bf, c1f);
    }
    __syncthreads();    // all warps done reading A before C overlay

    #pragma unroll
    for (int t = 0; t < c0f.num_elements; ++t) {
        c0f.x[t] = fmaxf(c0f.x[t], 0.0f);
        c1f.x[t] = fmaxf(c1f.x[t], 0.0f);
    }
    wmma::store_matrix_sync(Cs + w * 16, c0f, SC, wmma::mem_row_major);
    wmma::store_matrix_sync(Cs + 16 * SC + w * 16, c1f, SC, wmma::mem_row_major);
    __syncthreads();

    // column-sum 32x128 -> partials
    {
        const int col  = tid & 127;
        const int part = tid >> 7;        // 0/1 -> 16-row bands
        float s = 0.f;
        #pragma unroll
        for (int rr = part * 16; rr < part * 16 + 16; ++rr)
            s += Cs[rr * SC + col];
        red[tid] = s;
    }
    __syncthreads();
    if (tid < 128)
        g_partials[blockIdx.x * D_DIM + tid] = red[tid] + red[tid + 128];
}

// ---------------- K4: reduce partials + softmax (float4, warp-parallel) ----
__global__ void final_kernel(float* __restrict__ out) {
    const int tid  = threadIdx.x;          // 512 threads = 16 warps
    const int w    = tid >> 5;
    const int lane = tid & 31;             // float4 column

    float4 acc = make_float4(0.f, 0.f, 0.f, 0.f);
    int t = w;
    for (; t + 16 < NTILES; t += 32) {
        float4 v0 = __ldg(((const float4*)(g_partials + t * D_DIM)) + lane);
        float4 v1 = __ldg(((const float4*)(g_partials + (t + 16) * D_DIM)) + lane);
        acc.x += v0.x + v1.x; acc.y += v0.y + v1.y;
        acc.z += v0.z + v1.z; acc.w += v0.w + v1.w;
    }
    if (t < NTILES) {
        float4 v = __ldg(((const float4*)(g_partials + t * D_DIM)) + lane);
        acc.x += v.x; acc.y += v.y; acc.z += v.z; acc.w += v.w;
    }

    __shared__ float4 sb[16][32];
    sb[w][lane] = acc;
    __syncthreads();

    if (w == 0) {
        float4 s = sb[0][lane];
        #pragma unroll
        for (int i = 1; i < 16; ++i) {
            float4 v = sb[i][lane];
            s.x += v.x; s.y += v.y; s.z += v.z; s.w += v.w;
        }
        float m = fmaxf(fmaxf(s.x, s.y), fmaxf(s.z, s.w));
        #pragma unroll
        for (int off = 16; off > 0; off >>= 1)
            m = fmaxf(m, __shfl_xor_sync(0xffffffffu, m, off));
        float e0 = expf(s.x - m), e1 = expf(s.y - m);
        float e2 = expf(s.z - m), e3 = expf(s.w - m);
        float sum = (e0 + e1) + (e2 + e3);
        #pragma unroll
        for (int off = 16; off > 0; off >>= 1)
            sum += __shfl_xor_sync(0xffffffffu, sum, off);
        float rinv = 1.0f / sum;
        ((float4*)out)[lane] = make_float4(e0 * rinv, e1 * rinv, e2 * rinv, e3 * rinv);
    }
}

// ---------------- launcher --------------------------------------------------
extern "C" void kernel_launch(void* const* d_in, const int* in_sizes, int n_in,
                              void* d_out, int out_size) {
    const int*   node_ids     = (const int*)d_in[0];
    const int*   neighbor_ids = (const int*)d_in[1];
    const int*   segment_ids  = (const int*)d_in[2];
    const float* W            = (const float*)d_in[3];
    const float* M            = (const float*)d_in[4];
    const float* emb          = (const float*)d_in[5];
    float*       out          = (float*)d_out;

    prep_kernel<<<PREP_BLOCKS, 256>>>(emb, W, M, segment_ids);
    gather_kernel<<<GBLKS, 256>>>(node_ids, neighbor_ids);
    gemm_kernel<<<NTILES, 256, A_BYTES>>>();
    final_kernel<<<1, 512>>>(out);
}

// round 10
// speedup vs baseline: 1.1839x; 1.1839x over previous
#include <cuda_runtime.h>
#include <cuda_bf16.h>
#include <mma.h>
#include <math.h>

using namespace nvcuda;

#define D_DIM 128
#define V_DIM 100000
#define N_DIM 20000
#define E_DIM 640000
#define NODES_PER_BLK 32
#define NTILES (N_DIM / NODES_PER_BLK)     // 625, exact

// padded strides (conflict-free LDSM: 528B row shift = 4 banks)
#define SA 264                  // bf16 elems per A row (528 B)
#define SC 132                  // float elems per C row (528 B)
#define A_BYTES   (NODES_PER_BLK * SA * 2)       // 16896 (== 32*SC*4, C overlay)
#define IDX_CAP   1600                           // staged edge indices (mean 1024)
#define IDX_BYTES (IDX_CAP * 4)
#define DYN_BYTES (A_BYTES + IDX_BYTES)          // 23296

// two-stage reduction
#define R1_BLOCKS 64
#define TILES_PER_R1 ((NTILES + R1_BLOCKS - 1) / R1_BLOCKS)   // 10

// prep kernel block ranges (epack: 8 float4 loads -> 4 uint4 stores / thread)
#define EPACK_T      400000     // float4-pair stride: pairs (t, t+EPACK_T*...)...
#define EPACK_BLOCKS 1563       // 400000/256 rounded up; thread t handles 4 pairs
#define WM_BLOCKS    32
#define RP_BLOCKS    2500
#define PREP_BLOCKS  (EPACK_BLOCKS + WM_BLOCKS + RP_BLOCKS)

// ---------------- scratch (device globals; no runtime allocation) ----------
__device__ int   g_rowptr[N_DIM + 1];
__device__ __nv_bfloat16 g_embh[(size_t)V_DIM * D_DIM];      // 25.6 MB bf16 table
__device__ __nv_bfloat16 g_wm[D_DIM * 2 * D_DIM];            // [128][256] bf16
__device__ float g_partials[NTILES * D_DIM];
__device__ float g_p2[R1_BLOCKS * D_DIM];

// ---------------- K1: prep (pack emb->bf16, pack [W|M], rowptr) ------------
// epack: thread handles 4 pairs of adjacent float4s -> 4 uint4 (16B) stores.
__global__ void prep_kernel(const float* __restrict__ emb,
                            const float* __restrict__ W,
                            const float* __restrict__ M,
                            const int* __restrict__ seg) {
    const int b   = blockIdx.x;
    const int tid = threadIdx.x;

    if (b < EPACK_BLOCKS) {
        const int t = b * 256 + tid;              // pair index 0 .. 400127
        if (t < EPACK_T) {
            const float4* src = (const float4*)emb;   // 3.2M float4s = 1.6M pairs
            // pair p -> float4s (2p, 2p+1); 4 pairs strided by EPACK_T
            float4 a[4], c[4];
            #pragma unroll
            for (int k = 0; k < 4; ++k) {
                size_t p = (size_t)t + (size_t)k * EPACK_T;
                a[k] = __ldg(src + 2 * p);
                c[k] = __ldg(src + 2 * p + 1);
            }
            #pragma unroll
            for (int k = 0; k < 4; ++k) {
                __nv_bfloat162 b0 = __float22bfloat162_rn(make_float2(a[k].x, a[k].y));
                __nv_bfloat162 b1 = __float22bfloat162_rn(make_float2(a[k].z, a[k].w));
                __nv_bfloat162 b2 = __float22bfloat162_rn(make_float2(c[k].x, c[k].y));
                __nv_bfloat162 b3 = __float22bfloat162_rn(make_float2(c[k].z, c[k].w));
                uint4 u;
                u.x = *(unsigned int*)&b0;
                u.y = *(unsigned int*)&b1;
                u.z = *(unsigned int*)&b2;
                u.w = *(unsigned int*)&b3;
                size_t p = (size_t)t + (size_t)k * EPACK_T;
                ((uint4*)g_embh)[p] = u;
            }
        }
    } else if (b < EPACK_BLOCKS + WM_BLOCKS) {
        int base = (b - EPACK_BLOCKS) * 256 + tid;
        #pragma unroll
        for (int rep = 0; rep < 4; ++rep) {
            int i = base + rep * 8192;            // 0..32767
            int d = i >> 8;
            int k = i & 255;
            float v = (k < D_DIM) ? __ldg(&W[d * D_DIM + k])
                                  : __ldg(&M[d * D_DIM + (k - D_DIM)]);
            g_wm[i] = __float2bfloat16(v);
        }
    } else {
        int e = (b - EPACK_BLOCKS - WM_BLOCKS) * 256 + tid;
        if (e >= E_DIM) return;
        int s = __ldg(&seg[e]);
        if (e == 0) {
            for (int t = 0; t <= s; ++t) g_rowptr[t] = 0;
        } else {
            int p = __ldg(&seg[e - 1]);
            for (int t = p + 1; t <= s; ++t) g_rowptr[t] = e;
        }
        if (e == E_DIM - 1) {
            for (int t = s + 1; t <= N_DIM; ++t) g_rowptr[t] = E_DIM;
        }
    }
}

// ---------------- helpers ---------------------------------------------------
__device__ __forceinline__ void acc_bf4(float acc[4], uint2 v) {
    float2 f0 = __bfloat1622float2(*(__nv_bfloat162*)&v.x);
    float2 f1 = __bfloat1622float2(*(__nv_bfloat162*)&v.y);
    acc[0] += f0.x; acc[1] += f0.y;
    acc[2] += f1.x; acc[3] += f1.y;
}

__device__ __forceinline__ uint2 pack_bf4(const float acc[4]) {
    __nv_bfloat162 b0 = __float22bfloat162_rn(make_float2(acc[0], acc[1]));
    __nv_bfloat162 b1 = __float22bfloat162_rn(make_float2(acc[2], acc[3]));
    uint2 u;
    u.x = *(unsigned int*)&b0;
    u.y = *(unsigned int*)&b1;
    return u;
}

// ---------------- K2: FUSED gather + segment-sum + GEMM + relu + colsum ----
// (unchanged from round 8 — best measured core)
__global__ __launch_bounds__(256)
void fused_kernel(const int* __restrict__ node_ids,
                  const int* __restrict__ nbr) {
    extern __shared__ unsigned char dynsmem[];
    __nv_bfloat16* As    = (__nv_bfloat16*)dynsmem;        // [32][SA]
    float*         Cs    = (float*)dynsmem;                // [32][SC] (overlay)
    int*           idx_s = (int*)(dynsmem + A_BYTES);      // [IDX_CAP]
    __shared__ float red[256];

    const int tid  = threadIdx.x;
    const int w    = tid >> 5;
    const int lane = tid & 31;
    const int n0   = blockIdx.x * NODES_PER_BLK;

    // ---------- Phase 0: stage edge indices ----------
    const int estart = g_rowptr[n0];
    const int ecnt   = g_rowptr[n0 + NODES_PER_BLK] - estart;
    const bool all_staged = (ecnt <= IDX_CAP);
    const int scnt   = all_staged ? ecnt : IDX_CAP;
    for (int j = tid; j < scnt; j += 256)
        idx_s[j] = __ldg(&nbr[estart + j]);
    __syncthreads();

    // ---------- Phase 1: gather + aggregate into A ----------
    #pragma unroll
    for (int i = 0; i < 4; ++i) {
        const int r = w * 4 + i;
        const int n = n0 + r;

        {
            int nid = __ldg(&node_ids[n]);
            uint2 sv = __ldg(((const uint2*)(g_embh + (size_t)nid * D_DIM)) + lane);
            *(uint2*)(As + r * SA + lane * 4) = sv;
        }

        float acc[4] = {0.f, 0.f, 0.f, 0.f};
        const int js = g_rowptr[n]     - estart;
        const int je = g_rowptr[n + 1] - estart;

        if (all_staged) {
            int j = js;
            for (; j + 16 <= je; j += 16) {
                int ix[16];
                #pragma unroll
                for (int k = 0; k < 16; ++k) ix[k] = idx_s[j + k];
                uint2 v[16];
                #pragma unroll
                for (int k = 0; k < 16; ++k)
                    v[k] = __ldg(((const uint2*)(g_embh + (size_t)ix[k] * D_DIM)) + lane);
                #pragma unroll
                for (int k = 0; k < 16; ++k) acc_bf4(acc, v[k]);
            }
            for (; j + 4 <= je; j += 4) {
                int ix[4];
                #pragma unroll
                for (int k = 0; k < 4; ++k) ix[k] = idx_s[j + k];
                uint2 v[4];
                #pragma unroll
                for (int k = 0; k < 4; ++k)
                    v[k] = __ldg(((const uint2*)(g_embh + (size_t)ix[k] * D_DIM)) + lane);
                #pragma unroll
                for (int k = 0; k < 4; ++k) acc_bf4(acc, v[k]);
            }
            for (; j < je; ++j) {
                uint2 v = __ldg(((const uint2*)(g_embh + (size_t)idx_s[j] * D_DIM)) + lane);
                acc_bf4(acc, v);
            }
        } else {
            for (int j = js; j < je; ++j) {
                int ix = (j < IDX_CAP) ? idx_s[j] : __ldg(&nbr[estart + j]);
                uint2 v = __ldg(((const uint2*)(g_embh + (size_t)ix * D_DIM)) + lane);
                acc_bf4(acc, v);
            }
        }
        *(uint2*)(As + r * SA + D_DIM + lane * 4) = pack_bf4(acc);
    }
    __syncthreads();

    // ---------- Phase 2: MMA (8 warps; warp w -> cols [16w,16w+16)) ----------
    wmma::fragment<wmma::accumulator, 16, 16, 16, float> c0f, c1f;
    wmma::fill_fragment(c0f, 0.0f);
    wmma::fill_fragment(c1f, 0.0f);

    #pragma unroll
    for (int kk = 0; kk < 16; ++kk) {
        wmma::fragment<wmma::matrix_b, 16, 16, 16, __nv_bfloat16, wmma::col_major> bf;
        wmma::load_matrix_sync(bf, g_wm + (w * 16) * 256 + kk * 16, 256);
        wmma::fragment<wmma::matrix_a, 16, 16, 16, __nv_bfloat16, wmma::row_major> a0, a1;
        wmma::load_matrix_sync(a0, As + kk * 16, SA);           // rows 0-15
        wmma::load_matrix_sync(a1, As + 16 * SA + kk * 16, SA); // rows 16-31
        wmma::mma_sync(c0f, a0, bf, c0f);
        wmma::mma_sync(c1f, a1, bf, c1f);
    }
    __syncthreads();

    #pragma unroll
    for (int t = 0; t < c0f.num_elements; ++t) {
        c0f.x[t] = fmaxf(c0f.x[t], 0.0f);
        c1f.x[t] = fmaxf(c1f.x[t], 0.0f);
    }
    wmma::store_matrix_sync(Cs + w * 16, c0f, SC, wmma::mem_row_major);
    wmma::store_matrix_sync(Cs + 16 * SC + w * 16, c1f, SC, wmma::mem_row_major);
    __syncthreads();

    {
        const int col  = tid & 127;
        const int part = tid >> 7;
        float s = 0.f;
        #pragma unroll
        for (int rr = part * 16; rr < part * 16 + 16; ++rr)
            s += Cs[rr * SC + col];
        red[tid] = s;
    }
    __syncthreads();
    if (tid < 128)
        g_partials[blockIdx.x * D_DIM + tid] = red[tid] + red[tid + 128];
}

// ---------------- K3: stage-1 reduce (64 blocks over 625 tile-rows) --------
__global__ __launch_bounds__(256)
void reduce1_kernel() {
    const int b   = blockIdx.x;
    const int tid = threadIdx.x;
    const int col  = tid & 127;
    const int half = tid >> 7;             // 0/1 split the tile list
    const int t0 = b * TILES_PER_R1;
    const int t1 = min(t0 + TILES_PER_R1, NTILES);

    float acc = 0.f;
    for (int t = t0 + half; t < t1; t += 2)
        acc += __ldg(&g_partials[t * D_DIM + col]);

    __shared__ float red[256];
    red[tid] = acc;
    __syncthreads();
    if (tid < 128)
        g_p2[b * D_DIM + tid] = red[tid] + red[tid + 128];
}

// ---------------- K4: stage-2 reduce + softmax ------------------------------
__global__ void final_kernel(float* __restrict__ out) {
    const int tid  = threadIdx.x;          // 512 threads = 16 warps
    const int w    = tid >> 5;
    const int lane = tid & 31;             // float4 column

    // 64 rows of g_p2, 16 warps -> 4 rows each (independent loads)
    float4 acc = make_float4(0.f, 0.f, 0.f, 0.f);
    #pragma unroll
    for (int k = 0; k < 4; ++k) {
        int t = w + k * 16;
        float4 v = __ldg(((const float4*)(g_p2 + t * D_DIM)) + lane);
        acc.x += v.x; acc.y += v.y; acc.z += v.z; acc.w += v.w;
    }

    __shared__ float4 sb[16][32];
    sb[w][lane] = acc;
    __syncthreads();

    if (w == 0) {
        float4 s = sb[0][lane];
        #pragma unroll
        for (int i = 1; i < 16; ++i) {
            float4 v = sb[i][lane];
            s.x += v.x; s.y += v.y; s.z += v.z; s.w += v.w;
        }
        float m = fmaxf(fmaxf(s.x, s.y), fmaxf(s.z, s.w));
        #pragma unroll
        for (int off = 16; off > 0; off >>= 1)
            m = fmaxf(m, __shfl_xor_sync(0xffffffffu, m, off));
        float e0 = expf(s.x - m), e1 = expf(s.y - m);
        float e2 = expf(s.z - m), e3 = expf(s.w - m);
        float sum = (e0 + e1) + (e2 + e3);
        #pragma unroll
        for (int off = 16; off > 0; off >>= 1)
            sum += __shfl_xor_sync(0xffffffffu, sum, off);
        float rinv = 1.0f / sum;
        ((float4*)out)[lane] = make_float4(e0 * rinv, e1 * rinv, e2 * rinv, e3 * rinv);
    }
}

// ---------------- launcher --------------------------------------------------
extern "C" void kernel_launch(void* const* d_in, const int* in_sizes, int n_in,
                              void* d_out, int out_size) {
    const int*   node_ids     = (const int*)d_in[0];
    const int*   neighbor_ids = (const int*)d_in[1];
    const int*   segment_ids  = (const int*)d_in[2];
    const float* W            = (const float*)d_in[3];
    const float* M            = (const float*)d_in[4];
    const float* emb          = (const float*)d_in[5];
    float*       out          = (float*)d_out;

    prep_kernel<<<PREP_BLOCKS, 256>>>(emb, W, M, segment_ids);
    fused_kernel<<<NTILES, 256, DYN_BYTES>>>(node_ids, neighbor_ids);
    reduce1_kernel<<<R1_BLOCKS, 256>>>();
    final_kernel<<<1, 512>>>(out);
}

// round 11
// speedup vs baseline: 1.2192x; 1.0298x over previous
#include <cuda_runtime.h>
#include <cuda_bf16.h>
#include <mma.h>
#include <math.h>

using namespace nvcuda;

#define D_DIM 128
#define V_DIM 100000
#define N_DIM 20000
#define E_DIM 640000
#define NODES_PER_BLK 32
#define NTILES (N_DIM / NODES_PER_BLK)     // 625, exact

// padded strides (conflict-free LDSM: 528B row shift = 4 banks)
#define SA 264                  // bf16 elems per A row (528 B)
#define SC 132                  // float elems per C row (528 B)
#define A_BYTES   (NODES_PER_BLK * SA * 2)       // 16896 (== 32*SC*4, C overlay)
#define IDX_CAP   1600                           // staged edge indices (mean 1024)
#define IDX_BYTES (IDX_CAP * 4)
#define DYN_BYTES (A_BYTES + IDX_BYTES)          // 23296

// two-stage reduction
#define R1_BLOCKS 64
#define TILES_PER_R1 ((NTILES + R1_BLOCKS - 1) / R1_BLOCKS)   // 10

// prep kernel block ranges (WM pack + rowptr only; no emb copy anymore)
#define WM_BLOCKS    32
#define RP_BLOCKS    2500
#define PREP_BLOCKS  (WM_BLOCKS + RP_BLOCKS)

// ---------------- scratch (device globals; no runtime allocation) ----------
__device__ int   g_rowptr[N_DIM + 1];
__device__ __nv_bfloat16 g_wm[D_DIM * 2 * D_DIM];            // [128][256] bf16
__device__ float g_partials[NTILES * D_DIM];
__device__ float g_p2[R1_BLOCKS * D_DIM];

// ---------------- K1: prep (pack [W|M], rowptr) -----------------------------
__global__ void prep_kernel(const float* __restrict__ W,
                            const float* __restrict__ M,
                            const int* __restrict__ seg) {
    const int b   = blockIdx.x;
    const int tid = threadIdx.x;

    if (b < WM_BLOCKS) {
        int base = b * 256 + tid;
        #pragma unroll
        for (int rep = 0; rep < 4; ++rep) {
            int i = base + rep * 8192;            // 0..32767
            int d = i >> 8;
            int k = i & 255;
            float v = (k < D_DIM) ? __ldg(&W[d * D_DIM + k])
                                  : __ldg(&M[d * D_DIM + (k - D_DIM)]);
            g_wm[i] = __float2bfloat16(v);
        }
    } else {
        int e = (b - WM_BLOCKS) * 256 + tid;
        if (e >= E_DIM) return;
        int s = __ldg(&seg[e]);
        if (e == 0) {
            for (int t = 0; t <= s; ++t) g_rowptr[t] = 0;
        } else {
            int p = __ldg(&seg[e - 1]);
            for (int t = p + 1; t <= s; ++t) g_rowptr[t] = e;
        }
        if (e == E_DIM - 1) {
            for (int t = s + 1; t <= N_DIM; ++t) g_rowptr[t] = E_DIM;
        }
    }
}

// ---------------- helpers ---------------------------------------------------
__device__ __forceinline__ uint2 pack_bf4(float x, float y, float z, float w) {
    __nv_bfloat162 b0 = __float22bfloat162_rn(make_float2(x, y));
    __nv_bfloat162 b1 = __float22bfloat162_rn(make_float2(z, w));
    uint2 u;
    u.x = *(unsigned int*)&b0;
    u.y = *(unsigned int*)&b1;
    return u;
}

// ---------------- K2: FUSED gather + segment-sum + GEMM + relu + colsum ----
// One block per 32-node tile, 256 threads = 8 warps.
// Phase 0: stage the tile's contiguous edge-index range into smem.
// Phase 1: warp w owns rows [4w,4w+4). Gather DIRECTLY from the fp32 emb
//   table (no bf16 copy): lane = float4 (16B) chunk of the 512B row; edge
//   loop unrolled x12 -> 12 independent LDG.128 in flight per warp (6KB
//   outstanding). fp32 accumulate; convert to bf16 only at the A-tile store.
// Phase 2: warp w computes cols [16w,16w+16) x rows 0..31. B from g_wm (L1).
// Phase 3: relu -> C overlay -> column-sum -> per-block partials.
__global__ __launch_bounds__(256)
void fused_kernel(const int* __restrict__ node_ids,
                  const int* __restrict__ nbr,
                  const float* __restrict__ emb) {
    extern __shared__ unsigned char dynsmem[];
    __nv_bfloat16* As    = (__nv_bfloat16*)dynsmem;        // [32][SA]
    float*         Cs    = (float*)dynsmem;                // [32][SC] (overlay)
    int*           idx_s = (int*)(dynsmem + A_BYTES);      // [IDX_CAP]
    __shared__ float red[256];

    const int tid  = threadIdx.x;
    const int w    = tid >> 5;
    const int lane = tid & 31;
    const int n0   = blockIdx.x * NODES_PER_BLK;

    // ---------- Phase 0: stage edge indices ----------
    const int estart = g_rowptr[n0];
    const int ecnt   = g_rowptr[n0 + NODES_PER_BLK] - estart;
    const bool all_staged = (ecnt <= IDX_CAP);
    const int scnt   = all_staged ? ecnt : IDX_CAP;
    for (int j = tid; j < scnt; j += 256)
        idx_s[j] = __ldg(&nbr[estart + j]);
    __syncthreads();

    // ---------- Phase 1: gather + aggregate into A (fp32 table) ----------
    #pragma unroll
    for (int i = 0; i < 4; ++i) {
        const int r = w * 4 + i;
        const int n = n0 + r;

        // self row: fp32 load -> bf16 store (32 lanes x 16B = 512B)
        {
            int nid = __ldg(&node_ids[n]);
            float4 sv = __ldg(((const float4*)(emb + (size_t)nid * D_DIM)) + lane);
            *(uint2*)(As + r * SA + lane * 4) = pack_bf4(sv.x, sv.y, sv.z, sv.w);
        }

        float4 acc = make_float4(0.f, 0.f, 0.f, 0.f);
        const int js = g_rowptr[n]     - estart;
        const int je = g_rowptr[n + 1] - estart;

        if (all_staged) {
            int j = js;
            // 12 independent LDG.128 gathers in flight (6KB/warp)
            for (; j + 12 <= je; j += 12) {
                int ix[12];
                #pragma unroll
                for (int k = 0; k < 12; ++k) ix[k] = idx_s[j + k];
                float4 v[12];
                #pragma unroll
                for (int k = 0; k < 12; ++k)
                    v[k] = __ldg(((const float4*)(emb + (size_t)ix[k] * D_DIM)) + lane);
                #pragma unroll
                for (int k = 0; k < 12; ++k) {
                    acc.x += v[k].x; acc.y += v[k].y;
                    acc.z += v[k].z; acc.w += v[k].w;
                }
            }
            for (; j + 4 <= je; j += 4) {
                int ix[4];
                #pragma unroll
                for (int k = 0; k < 4; ++k) ix[k] = idx_s[j + k];
                float4 v[4];
                #pragma unroll
                for (int k = 0; k < 4; ++k)
                    v[k] = __ldg(((const float4*)(emb + (size_t)ix[k] * D_DIM)) + lane);
                #pragma unroll
                for (int k = 0; k < 4; ++k) {
                    acc.x += v[k].x; acc.y += v[k].y;
                    acc.z += v[k].z; acc.w += v[k].w;
                }
            }
            for (; j < je; ++j) {
                float4 v = __ldg(((const float4*)(emb + (size_t)idx_s[j] * D_DIM)) + lane);
                acc.x += v.x; acc.y += v.y; acc.z += v.z; acc.w += v.w;
            }
        } else {
            for (int j = js; j < je; ++j) {
                int ix = (j < IDX_CAP) ? idx_s[j] : __ldg(&nbr[estart + j]);
                float4 v = __ldg(((const float4*)(emb + (size_t)ix * D_DIM)) + lane);
                acc.x += v.x; acc.y += v.y; acc.z += v.z; acc.w += v.w;
            }
        }
        *(uint2*)(As + r * SA + D_DIM + lane * 4) =
            pack_bf4(acc.x, acc.y, acc.z, acc.w);
    }
    __syncthreads();

    // ---------- Phase 2: MMA (8 warps; warp w -> cols [16w,16w+16)) ----------
    wmma::fragment<wmma::accumulator, 16, 16, 16, float> c0f, c1f;
    wmma::fill_fragment(c0f, 0.0f);
    wmma::fill_fragment(c1f, 0.0f);

    #pragma unroll
    for (int kk = 0; kk < 16; ++kk) {
        wmma::fragment<wmma::matrix_b, 16, 16, 16, __nv_bfloat16, wmma::col_major> bf;
        wmma::load_matrix_sync(bf, g_wm + (w * 16) * 256 + kk * 16, 256);
        wmma::fragment<wmma::matrix_a, 16, 16, 16, __nv_bfloat16, wmma::row_major> a0, a1;
        wmma::load_matrix_sync(a0, As + kk * 16, SA);           // rows 0-15
        wmma::load_matrix_sync(a1, As + 16 * SA + kk * 16, SA); // rows 16-31
        wmma::mma_sync(c0f, a0, bf, c0f);
        wmma::mma_sync(c1f, a1, bf, c1f);
    }
    __syncthreads();    // all warps done reading A before C overlay

    #pragma unroll
    for (int t = 0; t < c0f.num_elements; ++t) {
        c0f.x[t] = fmaxf(c0f.x[t], 0.0f);
        c1f.x[t] = fmaxf(c1f.x[t], 0.0f);
    }
    wmma::store_matrix_sync(Cs + w * 16, c0f, SC, wmma::mem_row_major);
    wmma::store_matrix_sync(Cs + 16 * SC + w * 16, c1f, SC, wmma::mem_row_major);
    __syncthreads();

    // ---------- Phase 3: column-sum 32x128 -> partials ----------
    {
        const int col  = tid & 127;
        const int part = tid >> 7;        // 0/1 -> 16-row bands
        float s = 0.f;
        #pragma unroll
        for (int rr = part * 16; rr < part * 16 + 16; ++rr)
            s += Cs[rr * SC + col];
        red[tid] = s;
    }
    __syncthreads();
    if (tid < 128)
        g_partials[blockIdx.x * D_DIM + tid] = red[tid] + red[tid + 128];
}

// ---------------- K3: stage-1 reduce (64 blocks over 625 tile-rows) --------
__global__ __launch_bounds__(256)
void reduce1_kernel() {
    const int b   = blockIdx.x;
    const int tid = threadIdx.x;
    const int col  = tid & 127;
    const int half = tid >> 7;             // 0/1 split the tile list
    const int t0 = b * TILES_PER_R1;
    const int t1 = min(t0 + TILES_PER_R1, NTILES);

    float acc = 0.f;
    for (int t = t0 + half; t < t1; t += 2)
        acc += __ldg(&g_partials[t * D_DIM + col]);

    __shared__ float red[256];
    red[tid] = acc;
    __syncthreads();
    if (tid < 128)
        g_p2[b * D_DIM + tid] = red[tid] + red[tid + 128];
}

// ---------------- K4: stage-2 reduce + softmax ------------------------------
__global__ void final_kernel(float* __restrict__ out) {
    const int tid  = threadIdx.x;          // 512 threads = 16 warps
    const int w    = tid >> 5;
    const int lane = tid & 31;             // float4 column

    float4 acc = make_float4(0.f, 0.f, 0.f, 0.f);
    #pragma unroll
    for (int k = 0; k < 4; ++k) {
        int t = w + k * 16;
        float4 v = __ldg(((const float4*)(g_p2 + t * D_DIM)) + lane);
        acc.x += v.x; acc.y += v.y; acc.z += v.z; acc.w += v.w;
    }

    __shared__ float4 sb[16][32];
    sb[w][lane] = acc;
    __syncthreads();

    if (w == 0) {
        float4 s = sb[0][lane];
        #pragma unroll
        for (int i = 1; i < 16; ++i) {
            float4 v = sb[i][lane];
            s.x += v.x; s.y += v.y; s.z += v.z; s.w += v.w;
        }
        float m = fmaxf(fmaxf(s.x, s.y), fmaxf(s.z, s.w));
        #pragma unroll
        for (int off = 16; off > 0; off >>= 1)
            m = fmaxf(m, __shfl_xor_sync(0xffffffffu, m, off));
        float e0 = expf(s.x - m), e1 = expf(s.y - m);
        float e2 = expf(s.z - m), e3 = expf(s.w - m);
        float sum = (e0 + e1) + (e2 + e3);
        #pragma unroll
        for (int off = 16; off > 0; off >>= 1)
            sum += __shfl_xor_sync(0xffffffffu, sum, off);
        float rinv = 1.0f / sum;
        ((float4*)out)[lane] = make_float4(e0 * rinv, e1 * rinv, e2 * rinv, e3 * rinv);
    }
}

// ---------------- launcher --------------------------------------------------
extern "C" void kernel_launch(void* const* d_in, const int* in_sizes, int n_in,
                              void* d_out, int out_size) {
    const int*   node_ids     = (const int*)d_in[0];
    const int*   neighbor_ids = (const int*)d_in[1];
    const int*   segment_ids  = (const int*)d_in[2];
    const float* W            = (const float*)d_in[3];
    const float* M            = (const float*)d_in[4];
    const float* emb          = (const float*)d_in[5];
    float*       out          = (float*)d_out;

    prep_kernel<<<PREP_BLOCKS, 256>>>(W, M, segment_ids);
    fused_kernel<<<NTILES, 256, DYN_BYTES>>>(node_ids, neighbor_ids, emb);
    reduce1_kernel<<<R1_BLOCKS, 256>>>();
    final_kernel<<<1, 512>>>(out);
}